// round 7
// baseline (speedup 1.0000x reference)
#include <cuda_runtime.h>
#include <cstdint>
#include <cstddef>

#define FULLMASK 0xFFFFFFFFu

namespace {
constexpr int      HW      = 4096;   // 64*64
constexpr unsigned KSEL    = 409;    // int(0.1 * 4096)
constexpr int      NTHREAD = 256;
constexpr int      NWARP   = 8;
constexpr int      CAP     = 1024;   // candidate list capacity (mean 546, std 21.7)
constexpr int      TCAP    = 64;     // tie-list capacity for the selected bin
// Integer bin over the magnitude key s = u<<1 (sign shifted out):
//   bin = (s >> 15) - BINBASE,  BINBASE = (bits(1.5f)<<1) >> 15 = 65280.
// bin 0   <=> |x| < 1.50098  -- uncounted; ~6 sigma below the 409th |x| of an
//             N(0,1) row.  bin 255 <=> |x| >= 1.99902 via clamp (fallback if hit).
// Bin boundaries are exact in key space: membership test is s - slo < 2^15.
constexpr int      BINBASE = 65280;  // 0x7F800000 >> 15
}

struct SmemT {
    unsigned hist[256];
    unsigned wsum[NWARP];
    unsigned cnt;        // candidate count (elements with bin >= 1)
    unsigned tcnt;       // tie-list count (elements in the selected bin)
    unsigned sel;        // selected bin (0xFFFFFFFF = none)
    unsigned r2;         // rank within selected bin
    unsigned Ts;         // threshold key (|x| bits << 1)
    unsigned inv_star;   // inverted-index cutoff for exact ties
    unsigned cs[CAP];    // candidate keys
    unsigned cinv[CAP];  // candidate inverted indices
    unsigned ts_[TCAP];
    unsigned tinv[TCAP];
};

// Block-wide total of per-thread count c (broadcast). Fallback path only.
__device__ __forceinline__ unsigned blk_total(SmemT* sm, unsigned c, int lane, int wid) {
    c = __reduce_add_sync(FULLMASK, c);
    __syncthreads();               // protect wsum reuse across calls
    if (lane == 0) sm->wsum[wid] = c;
    __syncthreads();
    unsigned t = 0;
#pragma unroll
    for (int w = 0; w < NWARP; w++) t += sm->wsum[w];
    return t;
}

__global__ void __launch_bounds__(NTHREAD, 8)
topk_sparse_kernel(const float* __restrict__ x, float* __restrict__ y)
{
    __shared__ SmemT sm;
    const int tid  = threadIdx.x;
    const int lane = tid & 31;
    const int wid  = tid >> 5;
    const size_t rowbase = (size_t)blockIdx.x * (HW / 4);
    const uint4* xin  = reinterpret_cast<const uint4*>(x) + rowbase;
    uint4*       yout = reinterpret_cast<uint4*>(y) + rowbase;
    // element (j,c) at linear idx 4*tid + 1024*j + c; inv = 4095 - idx
    const unsigned invbase = 4095u - ((unsigned)tid << 2);

    // ---- load row (4 x LDG.128, front-batched for MLP) ----
    uint4 t0 = xin[tid];
    uint4 t1 = xin[tid + 256];
    uint4 t2 = xin[tid + 512];
    uint4 t3 = xin[tid + 768];

    sm.hist[tid] = 0;
    if (tid == 0) { sm.cnt = 0; sm.tcnt = 0; sm.sel = 0xFFFFFFFFu; }
    __syncthreads();

    // ---- one pass: histogram + warp-aggregated candidate compaction ----
    {
        unsigned uu[16] = { t0.x, t0.y, t0.z, t0.w,  t1.x, t1.y, t1.z, t1.w,
                            t2.x, t2.y, t2.z, t2.w,  t3.x, t3.y, t3.z, t3.w };
#pragma unroll
        for (int e = 0; e < 16; e++) {
            unsigned s = uu[e] << 1;
            int b = (int)(s >> 15) - BINBASE;
            bool pred = (b >= 1);
            if (pred) atomicAdd(&sm.hist[min(b, 255)], 1u);  // flat predicated ATOMS
            unsigned mask = __ballot_sync(FULLMASK, pred);
            if (pred) {
                int leader = __ffs(mask) - 1;
                unsigned base;
                if (lane == leader) base = atomicAdd(&sm.cnt, (unsigned)__popc(mask));
                base = __shfl_sync(mask, base, leader);
                unsigned pos = base + (unsigned)__popc(mask & ((1u << lane) - 1u));
                if (pos < (unsigned)CAP) {
                    sm.cs[pos]   = s;
                    sm.cinv[pos] = invbase - (unsigned)(((e >> 2) << 10) + (e & 3));
                }
            }
        }
    }
    __syncthreads();

    // ---- descending cumulative scan over 256 bins ----
    {
        int b = 255 - tid;
        unsigned cb = (b >= 1) ? sm.hist[b] : 0u;   // bin 0 uncounted by design
        unsigned incl = cb;
#pragma unroll
        for (int d = 1; d < 32; d <<= 1) {
            unsigned n = __shfl_up_sync(FULLMASK, incl, d);
            if (lane >= d) incl += n;
        }
        if (lane == 31) sm.wsum[wid] = incl;
        __syncthreads();
#pragma unroll
        for (int w = 0; w < NWARP - 1; w++)
            if (w < wid) incl += sm.wsum[w];
        unsigned excl = incl - cb;
        if (excl < KSEL && KSEL <= incl) { sm.sel = (unsigned)b; sm.r2 = KSEL - excl; }
    }
    __syncthreads();

    // ---- filter candidate list down to the selected bin (~1.7 expected) ----
    const unsigned m   = sm.cnt;
    const unsigned slo = (sm.sel + (unsigned)BINBASE) << 15;  // garbage if sel invalid -> no hits
    const unsigned mc  = m < (unsigned)CAP ? m : (unsigned)CAP;
    for (unsigned i = tid; i < mc; i += NTHREAD) {
        unsigned s = sm.cs[i];
        if (s - slo < (1u << 15)) {
            unsigned pos = atomicAdd(&sm.tcnt, 1u);
            if (pos < (unsigned)TCAP) { sm.ts_[pos] = s; sm.tinv[pos] = sm.cinv[i]; }
        }
    }
    __syncthreads();

    const bool fb = (sm.sel == 0xFFFFFFFFu) || (sm.sel >= 255u) ||
                    (m > (unsigned)CAP) || (sm.tcnt > (unsigned)TCAP);
    if (!fb) {
        // ---- exact selection of rank r2 within the bin (ties by index) ----
        const unsigned m2 = sm.tcnt;
        const unsigned r2 = sm.r2;
        if ((unsigned)tid < m2) {
            unsigned si = sm.ts_[tid], vi = sm.tinv[tid];
            unsigned rank = 0;
            for (unsigned j = 0; j < m2; j++) {
                unsigned sj = sm.ts_[j], vj = sm.tinv[j];
                rank += (sj > si || (sj == si && vj > vi)) ? 1u : 0u;
            }
            if (rank == r2 - 1u) { sm.Ts = si; sm.inv_star = vi; }
        }
    } else {
        // ---- exact fallback: bitwise binary search (block-uniform, L2 re-reads) ----
        unsigned lo = 0;                       // s values are even; bit0 skipped
        for (int bit = 31; bit >= 1; bit--) {
            unsigned T = lo | (1u << bit);
            unsigned c = 0;
            for (int j = 0; j < 4; j++) {
                uint4 v = xin[tid + j * 256];
                c += ((v.x << 1) >= T) + ((v.y << 1) >= T) + ((v.z << 1) >= T) + ((v.w << 1) >= T);
            }
            if (blk_total(&sm, c, lane, wid) >= KSEL) lo = T;
        }
        const unsigned Tsf = lo;               // exact KSEL-th largest key
        unsigned cgt = 0;
        for (int j = 0; j < 4; j++) {
            uint4 v = xin[tid + j * 256];
            cgt += ((v.x << 1) > Tsf) + ((v.y << 1) > Tsf) + ((v.z << 1) > Tsf) + ((v.w << 1) > Tsf);
        }
        cgt = blk_total(&sm, cgt, lane, wid);
        const unsigned req = KSEL - cgt;       // >= 1 by construction
        unsigned vlo = 0;
        for (int bit = 11; bit >= 0; bit--) {
            unsigned V = vlo | (1u << bit);
            unsigned c = 0;
            for (int j = 0; j < 4; j++) {
                uint4 v = xin[tid + j * 256];
                unsigned w4[4] = { v.x, v.y, v.z, v.w };
                for (int cc = 0; cc < 4; cc++) {
                    unsigned inv = invbase - (unsigned)((j << 10) + cc);
                    c += (((w4[cc] << 1) == Tsf) && inv >= V) ? 1u : 0u;
                }
            }
            if (blk_total(&sm, c, lane, wid) >= req) vlo = V;
        }
        if (tid == 0) { sm.Ts = Tsf; sm.inv_star = vlo; }
    }
    __syncthreads();

    const unsigned Ts    = sm.Ts;
    const unsigned istar = sm.inv_star;

    // ---- masked write-back; row re-read hits L2 (~19MB in flight << 126MB) ----
#pragma unroll
    for (int j = 0; j < 4; j++) {
        uint4 v = xin[tid + j * 256];
        unsigned w4[4] = { v.x, v.y, v.z, v.w };
        unsigned o[4];
#pragma unroll
        for (int c = 0; c < 4; c++) {
            const unsigned s   = w4[c] << 1;
            const unsigned inv = invbase - (unsigned)((j << 10) + c);
            const bool keep = (s > Ts) || (s == Ts && inv >= istar);
            o[c] = keep ? w4[c] : 0u;
        }
        uint4 ov; ov.x = o[0]; ov.y = o[1]; ov.z = o[2]; ov.w = o[3];
        yout[tid + j * 256] = ov;
    }
}

extern "C" void kernel_launch(void* const* d_in, const int* in_sizes, int n_in,
                              void* d_out, int out_size) {
    const float* x = (const float*)d_in[0];
    float* y = (float*)d_out;
    const int nrows = in_sizes[0] / HW;   // 16384 rows of 4096
    topk_sparse_kernel<<<nrows, NTHREAD>>>(x, y);
}

// round 8
// speedup vs baseline: 1.6277x; 1.6277x over previous
#include <cuda_runtime.h>
#include <cstdint>
#include <cstddef>

#define FULLMASK 0xFFFFFFFFu

namespace {
constexpr int      HW      = 4096;   // 64*64
constexpr unsigned KSEL    = 409;    // int(0.1 * 4096)
constexpr int      NTHREAD = 256;
constexpr int      NWARP   = 8;
constexpr int      TCAP    = 64;     // tie-list capacity for the selected bin
// Integer bins of width 2^14 over the magnitude key s = u<<1 (sign shifted out),
// covering |x| in [1.5, 1.75):
//   bin = (s >> 14) - BINBASE,  BINBASE = (bits(1.5f)<<1) >> 14 = 130560.
// bin 0    <=> |x| < 1.50024  -- uncounted; ~6 sigma below the 409th |x| of N(0,1)
// bin >255 <=> |x| >= 1.75    -- counted in REGISTERS (c_hi), no atomics;
//              threshold >= 1.75 is ~4.6 sigma -> exact fallback if it happens.
// Boundaries are exact in key space: membership test is s - slo < 2^14.
constexpr int      BINBASE = 130560;      // 0x7F800000 >> 14
constexpr unsigned S_HI    = 0x7FC00000u; // key(1.75f) = bits(1.75)<<1
}

struct SmemT {
    uint4    data[HW / 4];   // 16KB row stash (each thread reads only its own words)
    unsigned hist[256];
    unsigned wsum[NWARP];
    unsigned whi[NWARP];     // per-warp totals of c_hi (elements >= 1.75)
    unsigned tcnt;
    unsigned sel;       // selected bin (0xFFFFFFFF = none)
    unsigned r2;        // rank within selected bin
    unsigned Ts;        // threshold key (|x| bits << 1)
    unsigned inv_star;  // inverted-index cutoff for exact ties
    unsigned ts_[TCAP];
    unsigned tinv[TCAP];
};

// Block-wide total of per-thread count c (broadcast). Fallback path only.
__device__ __forceinline__ unsigned blk_total(SmemT* sm, unsigned c, int lane, int wid) {
    c = __reduce_add_sync(FULLMASK, c);
    __syncthreads();               // protect wsum reuse across calls
    if (lane == 0) sm->wsum[wid] = c;
    __syncthreads();
    unsigned t = 0;
#pragma unroll
    for (int w = 0; w < NWARP; w++) t += sm->wsum[w];
    return t;
}

__global__ void __launch_bounds__(NTHREAD, 8)
topk_sparse_kernel(const float* __restrict__ x, float* __restrict__ y)
{
    __shared__ SmemT sm;
    const int tid  = threadIdx.x;
    const int lane = tid & 31;
    const int wid  = tid >> 5;
    const size_t rowbase = (size_t)blockIdx.x * (HW / 4);
    const uint4* xin  = reinterpret_cast<const uint4*>(x) + rowbase;
    uint4*       yout = reinterpret_cast<uint4*>(y) + rowbase;
    // element (j,c) at linear idx 4*tid + 1024*j + c; inv = 4095 - idx
    const unsigned invbase = 4095u - ((unsigned)tid << 2);

    // ---- load row (4 x LDG.128, front-batched for MLP), stash to smem ----
    uint4 t0 = xin[tid];
    uint4 t1 = xin[tid + 256];
    uint4 t2 = xin[tid + 512];
    uint4 t3 = xin[tid + 768];

    sm.hist[tid] = 0;
    if (tid == 0) { sm.tcnt = 0; sm.sel = 0xFFFFFFFFu; }

    sm.data[tid]       = t0;
    sm.data[tid + 256] = t1;
    sm.data[tid + 512] = t2;
    sm.data[tid + 768] = t3;
    __syncthreads();   // hist zeros visible before atomics

    // ---- histogram pass from in-flight registers; upper tail in registers ----
    {
        unsigned uu[16] = { t0.x, t0.y, t0.z, t0.w,  t1.x, t1.y, t1.z, t1.w,
                            t2.x, t2.y, t2.z, t2.w,  t3.x, t3.y, t3.z, t3.w };
        unsigned c_hi = 0;
#pragma unroll
        for (int e = 0; e < 16; e++) {
            unsigned s = uu[e] << 1;
            c_hi += (s >= S_HI) ? 1u : 0u;                 // register-side tail count
            unsigned bm1 = (s >> 14) - (unsigned)(BINBASE + 1);
            if (bm1 < 255u)                                 // bin in [1,255]
                atomicAdd(&sm.hist[bm1 + 1u], 1u);          // flat predicated ATOMS
        }
        c_hi = __reduce_add_sync(FULLMASK, c_hi);
        if (lane == 0) sm.whi[wid] = c_hi;
    }
    __syncthreads();

    // ---- rank offset from the register-counted tail ----
    unsigned chitot = 0;
#pragma unroll
    for (int w = 0; w < NWARP; w++) chitot += sm.whi[w];
    const bool fbhi = (chitot >= KSEL);          // threshold >= 1.75: fallback
    const unsigned r = KSEL - chitot;            // rank within [1.5, 1.75) bins

    // ---- descending cumulative scan over 256 bins ----
    {
        int b = 255 - tid;
        unsigned cb = (b >= 1) ? sm.hist[b] : 0u;   // bin 0 uncounted by design
        unsigned incl = cb;
#pragma unroll
        for (int d = 1; d < 32; d <<= 1) {
            unsigned n = __shfl_up_sync(FULLMASK, incl, d);
            if (lane >= d) incl += n;
        }
        if (lane == 31) sm.wsum[wid] = incl;
        __syncthreads();
#pragma unroll
        for (int w = 0; w < NWARP - 1; w++)
            if (w < wid) incl += sm.wsum[w];
        unsigned excl = incl - cb;
        if (!fbhi && excl < r && r <= incl) { sm.sel = (unsigned)b; sm.r2 = r - excl; }
    }
    __syncthreads();

    // ---- retrieval: 2-op range test against the selected bin's key range ----
    // (if sel is invalid, slo is garbage but fb is taken and pushes are unused)
    const unsigned slo = (sm.sel + (unsigned)BINBASE) << 14;
#pragma unroll
    for (int j = 0; j < 4; j++) {
        uint4 v = sm.data[tid + j * 256];
        unsigned w4[4] = { v.x, v.y, v.z, v.w };
#pragma unroll
        for (int c = 0; c < 4; c++) {
            unsigned s = w4[c] << 1;
            if (s - slo < (1u << 14)) {            // exact bin membership
                unsigned pos = atomicAdd(&sm.tcnt, 1u);
                if (pos < (unsigned)TCAP) {
                    sm.ts_[pos]  = s;
                    sm.tinv[pos] = invbase - (unsigned)((j << 10) + c);
                }
            }
        }
    }
    __syncthreads();

    const bool fb = fbhi || (sm.sel == 0xFFFFFFFFu) || (sm.tcnt > (unsigned)TCAP);
    if (!fb) {
        // ---- exact selection of rank r2 within the bin (ties by index) ----
        const unsigned m2 = sm.tcnt;
        const unsigned r2 = sm.r2;
        if ((unsigned)tid < m2) {
            unsigned si = sm.ts_[tid], vi = sm.tinv[tid];
            unsigned rank = 0;
            for (unsigned j = 0; j < m2; j++) {
                unsigned sj = sm.ts_[j], vj = sm.tinv[j];
                rank += (sj > si || (sj == si && vj > vi)) ? 1u : 0u;
            }
            if (rank == r2 - 1u) { sm.Ts = si; sm.inv_star = vi; }
        }
    } else {
        // ---- exact fallback: bitwise binary search (block-uniform, reads stash) ----
        unsigned lo = 0;                       // s values are even; bit0 skipped
        for (int bit = 31; bit >= 1; bit--) {
            unsigned T = lo | (1u << bit);
            unsigned c = 0;
            for (int j = 0; j < 4; j++) {
                uint4 v = sm.data[tid + j * 256];
                c += ((v.x << 1) >= T) + ((v.y << 1) >= T) + ((v.z << 1) >= T) + ((v.w << 1) >= T);
            }
            if (blk_total(&sm, c, lane, wid) >= KSEL) lo = T;
        }
        const unsigned Tsf = lo;               // exact KSEL-th largest key
        unsigned cgt = 0;
        for (int j = 0; j < 4; j++) {
            uint4 v = sm.data[tid + j * 256];
            cgt += ((v.x << 1) > Tsf) + ((v.y << 1) > Tsf) + ((v.z << 1) > Tsf) + ((v.w << 1) > Tsf);
        }
        cgt = blk_total(&sm, cgt, lane, wid);
        const unsigned req = KSEL - cgt;       // >= 1 by construction
        unsigned vlo = 0;
        for (int bit = 11; bit >= 0; bit--) {
            unsigned V = vlo | (1u << bit);
            unsigned c = 0;
            for (int j = 0; j < 4; j++) {
                uint4 v = sm.data[tid + j * 256];
                unsigned w4[4] = { v.x, v.y, v.z, v.w };
                for (int cc = 0; cc < 4; cc++) {
                    unsigned inv = invbase - (unsigned)((j << 10) + cc);
                    c += (((w4[cc] << 1) == Tsf) && inv >= V) ? 1u : 0u;
                }
            }
            if (blk_total(&sm, c, lane, wid) >= req) vlo = V;
        }
        if (tid == 0) { sm.Ts = Tsf; sm.inv_star = vlo; }
    }
    __syncthreads();

    const unsigned Ts    = sm.Ts;
    const unsigned istar = sm.inv_star;

    // ---- masked write-back from the smem stash ----
#pragma unroll
    for (int j = 0; j < 4; j++) {
        uint4 v = sm.data[tid + j * 256];
        unsigned w4[4] = { v.x, v.y, v.z, v.w };
        unsigned o[4];
#pragma unroll
        for (int c = 0; c < 4; c++) {
            const unsigned s   = w4[c] << 1;
            const unsigned inv = invbase - (unsigned)((j << 10) + c);
            const bool keep = (s > Ts) || (s == Ts && inv >= istar);
            o[c] = keep ? w4[c] : 0u;
        }
        uint4 ov; ov.x = o[0]; ov.y = o[1]; ov.z = o[2]; ov.w = o[3];
        yout[tid + j * 256] = ov;
    }
}

extern "C" void kernel_launch(void* const* d_in, const int* in_sizes, int n_in,
                              void* d_out, int out_size) {
    const float* x = (const float*)d_in[0];
    float* y = (float*)d_out;
    const int nrows = in_sizes[0] / HW;   // 16384 rows of 4096
    topk_sparse_kernel<<<nrows, NTHREAD>>>(x, y);
}